// round 5
// baseline (speedup 1.0000x reference)
#include <cuda_runtime.h>

// LightweightConv1d: x (B=8, T=4096, C=1024) fp32, weight (H=16,1,K=7) fp32.
// y[b,t,c] = sum_k softmax(w[c%H])[k] * x[b, t+k-3, c]
//
// R5: fine-grained blocks for load balance. 128-thread blocks (half the
// channel lanes) x 64-long T strips -> 1024 blocks (6.92/SM, balance 1.01).
// GRP=4 register window (~80 regs) -> occ 6 = 24 warps/SM, 96 loads in
// flight/SM. Halo 9.4%, evict-first stores.

#define CC   1024
#define HH   16
#define KK   7
#define PADP 3
#define TT   4096
#define BB   8
#define TCHUNK 64
#define GRP    4
#define C4     (CC / 4)     // 256 float4 lanes per t
#define BLKT   128          // threads per block (half the lanes)
#define CSPLIT (C4 / BLKT)  // 2 channel sub-blocks

__global__ __launch_bounds__(BLKT, 6) void lightconv_kernel(
    const float* __restrict__ x,
    const float* __restrict__ weight,
    float* __restrict__ out)
{
    const int tiles_per_b = TT / TCHUNK;                 // 64
    const int cblk = blockIdx.x % CSPLIT;                // which channel half
    const int tile = (blockIdx.x / CSPLIT) % tiles_per_b;
    const int b    = blockIdx.x / (CSPLIT * tiles_per_b);
    const int c4   = cblk * BLKT + threadIdx.x;          // 0..255
    const int t0   = tile * TCHUNK;

    // --- softmax of the 4 head kernels this float4 uses (heads h0..h0+3) ---
    const int h0 = (c4 * 4) % HH;
    float w0[KK], w1[KK], w2[KK], w3[KK];
    {
        float* wr[4] = {w0, w1, w2, w3};
        #pragma unroll
        for (int j = 0; j < 4; j++) {
            const int h = h0 + j;
            float m = -1e30f;
            #pragma unroll
            for (int k = 0; k < KK; k++) {
                wr[j][k] = weight[h * KK + k];
                m = fmaxf(m, wr[j][k]);
            }
            float s = 0.0f;
            #pragma unroll
            for (int k = 0; k < KK; k++) {
                wr[j][k] = __expf(wr[j][k] - m);
                s += wr[j][k];
            }
            const float inv = 1.0f / s;
            #pragma unroll
            for (int k = 0; k < KK; k++) wr[j][k] *= inv;
        }
    }

    const float4* __restrict__ xv =
        reinterpret_cast<const float4*>(x) + (size_t)b * TT * C4 + c4;
    float4* __restrict__ ov =
        reinterpret_cast<float4*>(out) + (size_t)b * TT * C4 + c4;

    const float4 z = make_float4(0.f, 0.f, 0.f, 0.f);

    // window: v[i] holds x[base - 3 + i]; v[0..5] carried, v[6..9] fresh
    float4 v[GRP + KK - 1];

    // prologue: v[0..5] = x[t0-3 .. t0+2]
    #pragma unroll
    for (int i = 0; i < KK - 1; i++) {
        const int t = t0 - PADP + i;
        v[i] = (t >= 0) ? xv[(size_t)t * C4] : z;   // high bound safe: t0+2 <= TT-62
    }

    #pragma unroll 1
    for (int g = 0; g < TCHUNK / GRP; g++) {
        const int base = t0 + g * GRP;

        // 4 independent loads, issued together
        #pragma unroll
        for (int i = 0; i < GRP; i++) {
            const int t = base + PADP + i;
            v[KK - 1 + i] = (t < TT) ? xv[(size_t)t * C4] : z;
        }

        #pragma unroll
        for (int j = 0; j < GRP; j++) {
            float4 acc = z;
            #pragma unroll
            for (int k = 0; k < KK; k++) {
                const float4 a = v[j + k];
                acc.x = fmaf(w0[k], a.x, acc.x);
                acc.y = fmaf(w1[k], a.y, acc.y);
                acc.z = fmaf(w2[k], a.z, acc.z);
                acc.w = fmaf(w3[k], a.w, acc.w);
            }
            // evict-first store: output is never re-read
            __stcs(&ov[(size_t)(base + j) * C4], acc);
        }

        // shift window tail
        #pragma unroll
        for (int i = 0; i < KK - 1; i++) v[i] = v[GRP + i];
    }
}

extern "C" void kernel_launch(void* const* d_in, const int* in_sizes, int n_in,
                              void* d_out, int out_size)
{
    const float* x = (const float*)d_in[0];      // (B, T, C) fp32
    const float* weight = (const float*)d_in[1]; // (H, 1, K) fp32
    float* out = (float*)d_out;                  // (B, T, C) fp32

    const int grid = BB * (TT / TCHUNK) * CSPLIT;   // 1024 blocks of 128 thr
    lightconv_kernel<<<grid, BLKT>>>(x, weight, out);
}

// round 6
// speedup vs baseline: 1.0825x; 1.0825x over previous
#include <cuda_runtime.h>

// LightweightConv1d: x (B=8, T=4096, C=1024) fp32, weight (H=16,1,K=7) fp32.
// y[b,t,c] = sum_k softmax(w[c%H])[k] * x[b, t+k-3, c]
//
// R6: 256-thread blocks (full 4KB contiguous channel row per t — strided
// sub-row streams proved 20% slower in R5). TCHUNK=128, GRP=16: per group a
// 64KB contiguous read burst then a 64KB write burst per block, minimizing
// DRAM read/write turnaround. Evict-first on both streams (pure streaming).

#define CC   1024
#define HH   16
#define KK   7
#define PADP 3
#define TT   4096
#define BB   8
#define TCHUNK 128
#define GRP    16
#define C4   (CC / 4)   // 256 float4 lanes per t -> blockDim.x

__global__ __launch_bounds__(C4, 2) void lightconv_kernel(
    const float* __restrict__ x,
    const float* __restrict__ weight,
    float* __restrict__ out)
{
    const int c4 = threadIdx.x;                 // 0..255
    const int tiles_per_b = TT / TCHUNK;        // 32
    const int b  = blockIdx.x / tiles_per_b;
    const int t0 = (blockIdx.x % tiles_per_b) * TCHUNK;

    // --- softmax of the 4 head kernels this float4 uses (heads h0..h0+3) ---
    const int h0 = (c4 * 4) % HH;
    float w0[KK], w1[KK], w2[KK], w3[KK];
    {
        float* wr[4] = {w0, w1, w2, w3};
        #pragma unroll
        for (int j = 0; j < 4; j++) {
            const int h = h0 + j;
            float m = -1e30f;
            #pragma unroll
            for (int k = 0; k < KK; k++) {
                wr[j][k] = weight[h * KK + k];
                m = fmaxf(m, wr[j][k]);
            }
            float s = 0.0f;
            #pragma unroll
            for (int k = 0; k < KK; k++) {
                wr[j][k] = __expf(wr[j][k] - m);
                s += wr[j][k];
            }
            const float inv = 1.0f / s;
            #pragma unroll
            for (int k = 0; k < KK; k++) wr[j][k] *= inv;
        }
    }

    const float4* __restrict__ xv =
        reinterpret_cast<const float4*>(x) + (size_t)b * TT * C4 + c4;
    float4* __restrict__ ov =
        reinterpret_cast<float4*>(out) + (size_t)b * TT * C4 + c4;

    const float4 z = make_float4(0.f, 0.f, 0.f, 0.f);

    // window: v[i] holds x[base - 3 + i]; v[0..5] carried, v[6..21] fresh
    float4 v[GRP + KK - 1];

    // prologue: v[0..5] = x[t0-3 .. t0+2]
    #pragma unroll
    for (int i = 0; i < KK - 1; i++) {
        const int t = t0 - PADP + i;
        v[i] = (t >= 0) ? __ldcs(&xv[(size_t)t * C4]) : z;
    }

    #pragma unroll 1
    for (int g = 0; g < TCHUNK / GRP; g++) {
        const int base = t0 + g * GRP;

        // 16 independent evict-first loads: one 64KB contiguous block burst
        #pragma unroll
        for (int i = 0; i < GRP; i++) {
            const int t = base + PADP + i;
            v[KK - 1 + i] = (t < TT) ? __ldcs(&xv[(size_t)t * C4]) : z;
        }

        // compute + one 64KB contiguous write burst
        #pragma unroll
        for (int j = 0; j < GRP; j++) {
            float4 acc = z;
            #pragma unroll
            for (int k = 0; k < KK; k++) {
                const float4 a = v[j + k];
                acc.x = fmaf(w0[k], a.x, acc.x);
                acc.y = fmaf(w1[k], a.y, acc.y);
                acc.z = fmaf(w2[k], a.z, acc.z);
                acc.w = fmaf(w3[k], a.w, acc.w);
            }
            __stcs(&ov[(size_t)(base + j) * C4], acc);
        }

        // shift window tail
        #pragma unroll
        for (int i = 0; i < KK - 1; i++) v[i] = v[GRP + i];
    }
}

extern "C" void kernel_launch(void* const* d_in, const int* in_sizes, int n_in,
                              void* d_out, int out_size)
{
    const float* x = (const float*)d_in[0];      // (B, T, C) fp32
    const float* weight = (const float*)d_in[1]; // (H, 1, K) fp32
    float* out = (float*)d_out;                  // (B, T, C) fp32

    const int grid = BB * (TT / TCHUNK);         // 256 blocks
    lightconv_kernel<<<grid, C4>>>(x, weight, out);
}

// round 8
// speedup vs baseline: 1.1298x; 1.0437x over previous
#include <cuda_runtime.h>

// LightweightConv1d: x (B=8, T=4096, C=1024) fp32, weight (H=16,1,K=7) fp32.
// y[b,t,c] = sum_k softmax(w[c%H])[k] * x[b, t+k-3, c]
//
// R7: scalar-channel design for maximum memory-level parallelism.
// Block = 1024 threads = one full channel row (4KB, fully coalesced:
// each warp-load = one 128B line). Thread = 1 channel -> head = c&15,
// only 7 weight registers. Tile = 32 t's, NO carried window: 38 guarded
// independent LDG.32 per tile (32 + 6 halo; halo hits L2, which holds the
// whole input). MLP=38/warp x 32 warps/SM -> ~9MB in flight chip-wide,
// saturating DRAM (prev kernels were demand-starved at ~69% DRAM active).
// Evict-first stores keep L2 for the input stream.

#define CC   1024
#define HH   16
#define KK   7
#define PADP 3
#define TT   4096
#define BB   8
#define TCHUNK 32
#define NROW (TCHUNK + KK - 1)   // 38

__global__ __launch_bounds__(1024, 1) void lightconv_kernel(
    const float* __restrict__ x,
    const float* __restrict__ weight,
    float* __restrict__ out)
{
    const int c = threadIdx.x;                  // 0..1023  (channel)
    const int tiles_per_b = TT / TCHUNK;        // 128
    const int b  = blockIdx.x / tiles_per_b;
    const int t0 = (blockIdx.x % tiles_per_b) * TCHUNK;

    // --- softmax of this channel's head kernel: 7 registers ---
    const int h = c & (HH - 1);
    float w[KK];
    {
        float m = -1e30f;
        #pragma unroll
        for (int k = 0; k < KK; k++) {
            w[k] = weight[h * KK + k];
            m = fmaxf(m, w[k]);
        }
        float s = 0.0f;
        #pragma unroll
        for (int k = 0; k < KK; k++) {
            w[k] = __expf(w[k] - m);
            s += w[k];
        }
        const float inv = 1.0f / s;
        #pragma unroll
        for (int k = 0; k < KK; k++) w[k] *= inv;
    }

    const float* __restrict__ xp  = x   + ((size_t)b * TT) * CC + c;
    float*       __restrict__ op  = out + ((size_t)b * TT) * CC + c;

    // --- 38 independent guarded loads, all issued back-to-back (MLP=38) ---
    float v[NROW];
    #pragma unroll
    for (int i = 0; i < NROW; i++) {
        const int t = t0 - PADP + i;
        v[i] = (t >= 0 && t < TT) ? xp[(size_t)t * CC] : 0.0f;
    }

    // --- 32 outputs ---
    #pragma unroll
    for (int j = 0; j < TCHUNK; j++) {
        float acc = 0.0f;
        #pragma unroll
        for (int k = 0; k < KK; k++)
            acc = fmaf(w[k], v[j + k], acc);
        __stcs(&op[(size_t)(t0 + j) * CC], acc);
    }
}

extern "C" void kernel_launch(void* const* d_in, const int* in_sizes, int n_in,
                              void* d_out, int out_size)
{
    const float* x = (const float*)d_in[0];      // (B, T, C) fp32
    const float* weight = (const float*)d_in[1]; // (H, 1, K) fp32
    float* out = (float*)d_out;                  // (B, T, C) fp32

    const int grid = BB * (TT / TCHUNK);         // 1024 blocks of 1024 thr
    lightconv_kernel<<<grid, 1024>>>(x, weight, out);
}